// round 3
// baseline (speedup 1.0000x reference)
#include <cuda_runtime.h>
#include <cstdint>

#define SOM_M    32
#define SOM_N    32
#define MN       1024
#define BATCH    2048
#define DIM      128
#define NITER_F  100.0f
#define ALPHA_F  0.3f
#define SIGMA_F  16.0f

// ---------------- scratch ----------------
__device__ unsigned long long g_bmu[BATCH];
__device__ float g_w2[MN];
__device__ float g_S[MN * DIM];
__device__ float g_cnt[MN];
__device__ float g_T[MN * DIM];          // [cx][by][d]
__device__ float g_tc[MN];               // [cx][by]

__device__ __forceinline__ unsigned int f2ord(float f) {
    unsigned int u = __float_as_uint(f);
    return (u & 0x80000000u) ? ~u : (u | 0x80000000u);
}

__device__ __forceinline__ void ffma2(unsigned long long& acc,
                                      unsigned long long a,
                                      unsigned long long b) {
    asm("fma.rn.f32x2 %0, %1, %2, %0;" : "+l"(acc) : "l"(a), "l"(b));
}

// ---------------- K0: reset scratch + w2 ----------------
__global__ void k_prep(const float* __restrict__ w) {
    int i = blockIdx.x * blockDim.x + threadIdx.x;   // 0..131071
    if (i < MN * DIM) g_S[i] = 0.0f;
    if (i < BATCH)    g_bmu[i] = 0xFFFFFFFFFFFFFFFFULL;
    if (i < MN)       g_cnt[i] = 0.0f;

    int warp = i >> 5;
    int lane = i & 31;
    if (warp < MN) {
        float4 v = *(const float4*)&w[warp * DIM + lane * 4];
        float s = v.x * v.x + v.y * v.y + v.z * v.z + v.w * v.w;
        #pragma unroll
        for (int o = 16; o >= 1; o >>= 1) s += __shfl_xor_sync(0xffffffffu, s, o);
        if (lane == 0) g_w2[warp] = s;
    }
}

// ---------------- K1: BMU GEMM + argmin ----------------
// tile 128m x 128b, 256 threads, 8m x 8b per thread.
// FFMA2 pairs packed along K: acc.lo = even-k partial, acc.hi = odd-k partial.
// Smem tiles stored row-natural (no transpose) with 16B-group XOR swizzle
// keyed on (row>>3)&7 so 8-row-strided column reads are bank-conflict-free.
__global__ __launch_bounds__(256, 1)
void k_bmu(const float* __restrict__ x, const float* __restrict__ w) {
    extern __shared__ float smem[];
    float* Ws = smem;                                   // 128*128 f
    float* Xs = smem + 128 * 128;                       // 128*128 f
    unsigned long long* Red =
        (unsigned long long*)(smem + 2 * 128 * 128);    // [16][128]

    const int m0 = blockIdx.x * 128;
    const int b0 = blockIdx.y * 128;
    const int tid = threadIdx.x;
    const int wrp = tid >> 5, lane = tid & 31;
    const int ty = (lane >> 2) | ((wrp & 1) << 3);      // 0..15 (8 distinct/warp)
    const int tx = (lane & 3) | ((wrp >> 1) << 2);      // 0..15 (4 distinct/warp)

    // stage both tiles (LDG.128 -> swizzled ST.128, full-rate)
    #pragma unroll
    for (int i = 0; i < 16; i++) {
        int idx = tid + i * 256;          // 0..4095
        int row = idx >> 5;               // 0..127
        int g   = idx & 31;               // float4 group
        int sg  = (g ^ ((row >> 3) & 7)) << 2;
        float4 v = *(const float4*)&w[(m0 + row) * DIM + g * 4];
        *(float4*)&Ws[row * 128 + sg] = v;
        float4 u = *(const float4*)&x[(b0 + row) * DIM + g * 4];
        *(float4*)&Xs[row * 128 + sg] = u;
    }
    __syncthreads();

    unsigned long long acc[8][8];
    #pragma unroll
    for (int mi = 0; mi < 8; mi++)
        #pragma unroll
        for (int bj = 0; bj < 8; bj++) acc[mi][bj] = 0ULL;

    const float* wbase = &Ws[(ty * 8) * 128];
    const float* xbase = &Xs[(tx * 8) * 128];
    const int sw = ty & 7;
    const int sx = tx & 7;

    #pragma unroll 1
    for (int kt = 0; kt < 32; kt++) {      // 4 k per step
        const int ow = (kt ^ sw) << 2;
        const int ox = (kt ^ sx) << 2;
        ulonglong2 xv[8];
        #pragma unroll
        for (int bj = 0; bj < 8; bj++)
            xv[bj] = *(const ulonglong2*)&xbase[bj * 128 + ox];
        #pragma unroll
        for (int mi = 0; mi < 8; mi++) {
            ulonglong2 wv = *(const ulonglong2*)&wbase[mi * 128 + ow];
            #pragma unroll
            for (int bj = 0; bj < 8; bj++) {
                ffma2(acc[mi][bj], wv.x, xv[bj].x);
                ffma2(acc[mi][bj], wv.y, xv[bj].y);
            }
        }
    }

    // epilogue: d2' = w2[m] - 2*(lo+hi); pack keys; min over this thread's 8 m
    float w2r[8];
    #pragma unroll
    for (int mi = 0; mi < 8; mi++) w2r[mi] = g_w2[m0 + ty * 8 + mi];

    #pragma unroll
    for (int bj = 0; bj < 8; bj++) {
        unsigned long long best = 0xFFFFFFFFFFFFFFFFULL;
        #pragma unroll
        for (int mi = 0; mi < 8; mi++) {
            float lo = __uint_as_float((unsigned int)(acc[mi][bj]));
            float hi = __uint_as_float((unsigned int)(acc[mi][bj] >> 32));
            float d2 = w2r[mi] - 2.0f * (lo + hi);
            unsigned long long key =
                ((unsigned long long)f2ord(d2) << 32) |
                (unsigned long long)(m0 + ty * 8 + mi);
            best = min(best, key);
        }
        Red[ty * 128 + tx * 8 + bj] = best;
    }
    __syncthreads();

    if (tid < 128) {
        unsigned long long best = Red[tid];
        #pragma unroll
        for (int t = 1; t < 16; t++) best = min(best, Red[t * 128 + tid]);
        atomicMin(&g_bmu[b0 + tid], best);
    }
}

// ---------------- K2: scatter x rows into BMU bins ----------------
__global__ void k_scatter(const float* __restrict__ x) {
    int warp = (blockIdx.x * blockDim.x + threadIdx.x) >> 5;  // 0..2047
    int lane = threadIdx.x & 31;
    if (warp >= BATCH) return;
    int m = (int)(g_bmu[warp] & 0xFFFFFFFFULL);
    float4 v = *(const float4*)&x[warp * DIM + lane * 4];
    float* dst = &g_S[m * DIM + lane * 4];
    asm volatile("red.global.add.v4.f32 [%0], {%1, %2, %3, %4};"
                 :: "l"(dst), "f"(v.x), "f"(v.y), "f"(v.z), "f"(v.w)
                 : "memory");
    if (lane == 0) atomicAdd(&g_cnt[m], 1.0f);
}

// ---------------- K3: x-direction gaussian contraction ----------------
// block = (cx-quad, by), 128 threads (d). 4 cx outputs share each g_S load.
__global__ __launch_bounds__(128)
void k_cx(const int* __restrict__ it) {
    __shared__ float e_s[32];
    const int cx0 = (blockIdx.x & 7) * 4;
    const int by  = blockIdx.x >> 3;
    const int d   = threadIdx.x;

    float lr_decay = 1.0f - (float)it[0] / NITER_F;
    float sig = SIGMA_F * lr_decay;
    float inv_s2 = 1.0f / (sig * sig);
    if (d < 32) e_s[d] = expf(-(float)(d * d) * inv_s2);
    __syncthreads();

    float a0 = 0.f, a1 = 0.f, a2 = 0.f, a3 = 0.f;
    #pragma unroll
    for (int bx = 0; bx < 32; bx++) {
        float s = g_S[(by * 32 + bx) * DIM + d];
        a0 += e_s[abs(cx0 + 0 - bx)] * s;
        a1 += e_s[abs(cx0 + 1 - bx)] * s;
        a2 += e_s[abs(cx0 + 2 - bx)] * s;
        a3 += e_s[abs(cx0 + 3 - bx)] * s;
    }
    g_T[((cx0 + 0) * 32 + by) * DIM + d] = a0;
    g_T[((cx0 + 1) * 32 + by) * DIM + d] = a1;
    g_T[((cx0 + 2) * 32 + by) * DIM + d] = a2;
    g_T[((cx0 + 3) * 32 + by) * DIM + d] = a3;

    if (d < 4) {
        float c = 0.f;
        #pragma unroll
        for (int bx = 0; bx < 32; bx++)
            c += e_s[abs(cx0 + d - bx)] * g_cnt[by * 32 + bx];
        g_tc[(cx0 + d) * 32 + by] = c;
    }
}

// ---------------- K4: y-direction contraction + final update ----------------
// block = (cy-quad, cx), 128 threads (d). 4 cy outputs share each g_T load.
__global__ __launch_bounds__(128)
void k_cy(const float* __restrict__ w,
          const int* __restrict__ it,
          float* __restrict__ out) {
    __shared__ float e_s[32];
    __shared__ float s_sh[4];
    const int cy0 = (blockIdx.x & 7) * 4;
    const int cx  = blockIdx.x >> 3;
    const int d   = threadIdx.x;

    float lr_decay = 1.0f - (float)it[0] / NITER_F;
    float alpha_op = ALPHA_F * lr_decay;
    float sig = SIGMA_F * lr_decay;
    float inv_s2 = 1.0f / (sig * sig);
    if (d < 32) e_s[d] = expf(-(float)(d * d) * inv_s2);
    __syncthreads();

    if (d < 4) {
        float s = 0.f;
        #pragma unroll
        for (int by = 0; by < 32; by++)
            s += e_s[abs(cy0 + d - by)] * g_tc[cx * 32 + by];
        s_sh[d] = s;
    }

    float a0 = 0.f, a1 = 0.f, a2 = 0.f, a3 = 0.f;
    #pragma unroll
    for (int by = 0; by < 32; by++) {
        float t = g_T[(cx * 32 + by) * DIM + d];
        a0 += e_s[abs(cy0 + 0 - by)] * t;
        a1 += e_s[abs(cy0 + 1 - by)] * t;
        a2 += e_s[abs(cy0 + 2 - by)] * t;
        a3 += e_s[abs(cy0 + 3 - by)] * t;
    }
    __syncthreads();

    #pragma unroll
    for (int q = 0; q < 4; q++) {
        float aq = (q == 0) ? a0 : (q == 1) ? a1 : (q == 2) ? a2 : a3;
        int c = (cy0 + q) * 32 + cx;
        float wv = w[c * DIM + d];
        out[c * DIM + d] = wv + alpha_op * aq - alpha_op * s_sh[q] * wv;
    }
}

// ---------------- launch ----------------
extern "C" void kernel_launch(void* const* d_in, const int* in_sizes, int n_in,
                              void* d_out, int out_size) {
    const float* x   = (const float*)d_in[0];   // [2048,128]
    const float* w   = (const float*)d_in[1];   // [1024,128]
    const int*   it  = (const int*)d_in[3];
    float* out = (float*)d_out;

    const int bmu_smem = 2 * 128 * 128 * 4 + 16 * 128 * 8;   // 147456 B
    cudaFuncSetAttribute(k_bmu, cudaFuncAttributeMaxDynamicSharedMemorySize,
                         bmu_smem);

    k_prep<<<512, 256>>>(w);
    k_bmu<<<dim3(8, 16), 256, bmu_smem>>>(x, w);
    k_scatter<<<256, 256>>>(x);
    k_cx<<<256, 128>>>(it);
    k_cy<<<256, 128>>>(w, it, out);
}